// round 2
// baseline (speedup 1.0000x reference)
#include <cuda_runtime.h>
#include <cstddef>

#define HID   1024
#define NH    16
#define HD    64
#define BATCH 2
#define SEQ   2048
#define BH    (BATCH*NH)       /* 32  */
#define MTOT  (BATCH*SEQ)      /* 4096 */

// Scratch for projected Q,K,V in [b,h,s,d] layout (16 MB each).
__device__ float g_Q[(size_t)BH*SEQ*HD];
__device__ float g_K[(size_t)BH*SEQ*HD];
__device__ float g_V[(size_t)BH*SEQ*HD];

// ---------------------------------------------------------------------------
// QKV projection: Y = X @ W^T + b, written into [b,h,s,d] scratch.
// X: [4096,1024] row-major, W: [1024(out),1024(in)] row-major.
// 128x128 tile, BK=8, 256 threads, 8x8 microtile.
// ---------------------------------------------------------------------------
__global__ __launch_bounds__(256) void qkv_gemm_kernel(
    const float* __restrict__ X,
    const float* __restrict__ Wq, const float* __restrict__ bq,
    const float* __restrict__ Wk, const float* __restrict__ bk,
    const float* __restrict__ Wv, const float* __restrict__ bv)
{
    const float* W; const float* bias; float* out;
    if (blockIdx.z == 0)      { W = Wq; bias = bq; out = g_Q; }
    else if (blockIdx.z == 1) { W = Wk; bias = bk; out = g_K; }
    else                      { W = Wv; bias = bv; out = g_V; }

    __shared__ float As[8][128];
    __shared__ float Bs[8][128];

    const int tid  = threadIdx.x;
    const int tx   = tid & 15;       // 0..15 -> N microtile
    const int ty   = tid >> 4;       // 0..15 -> M microtile
    const int lrow = tid >> 1;       // 0..127
    const int lk   = (tid & 1) * 4;  // 0 or 4

    const float* Xb = X + (size_t)(blockIdx.y * 128) * HID;
    const float* Wb = W + (size_t)(blockIdx.x * 128) * HID;

    float acc[8][8];
    #pragma unroll
    for (int i = 0; i < 8; i++)
        #pragma unroll
        for (int j = 0; j < 8; j++) acc[i][j] = 0.f;

    for (int k0 = 0; k0 < HID; k0 += 8) {
        float4 xa = *(const float4*)(Xb + (size_t)lrow * HID + k0 + lk);
        float4 wa = *(const float4*)(Wb + (size_t)lrow * HID + k0 + lk);
        __syncthreads();            // protect previous iteration's reads
        As[lk+0][lrow] = xa.x; As[lk+1][lrow] = xa.y;
        As[lk+2][lrow] = xa.z; As[lk+3][lrow] = xa.w;
        Bs[lk+0][lrow] = wa.x; Bs[lk+1][lrow] = wa.y;
        Bs[lk+2][lrow] = wa.z; Bs[lk+3][lrow] = wa.w;
        __syncthreads();
        #pragma unroll
        for (int k = 0; k < 8; k++) {
            float a[8], b[8];
            #pragma unroll
            for (int i = 0; i < 8; i++) a[i] = As[k][ty*8 + i];
            #pragma unroll
            for (int j = 0; j < 8; j++) b[j] = Bs[k][tx*8 + j];
            #pragma unroll
            for (int i = 0; i < 8; i++)
                #pragma unroll
                for (int j = 0; j < 8; j++) acc[i][j] += a[i] * b[j];
        }
    }

    #pragma unroll
    for (int i = 0; i < 8; i++) {
        const int m  = blockIdx.y * 128 + ty*8 + i;
        const int bb = m >> 11;         // /2048
        const int s  = m & (SEQ - 1);
        #pragma unroll
        for (int j = 0; j < 8; j++) {
            const int n = blockIdx.x * 128 + tx*8 + j;
            const int h = n >> 6;
            const int d = n & 63;
            out[(((size_t)(bb*NH + h) * SEQ) + s) * HD + d] = acc[i][j] + bias[n];
        }
    }
}

// ---------------------------------------------------------------------------
// Fused attention: one warp per query row (8 rows per block).
// Scores for all 2048 keys kept in registers (64/lane), one-pass softmax,
// single probs write, then ctx accumulation over smem V tiles.
// ---------------------------------------------------------------------------
__global__ __launch_bounds__(256) void attn_kernel(
    float* __restrict__ ctx_out, float* __restrict__ probs_out)
{
    __shared__ __align__(16) float tile[64][68];  // K/V tile, padded
    __shared__ __align__(16) float qrow[8][64];
    __shared__ __align__(16) float prow[8][64];

    const int tid  = threadIdx.x;
    const int w    = tid >> 5;
    const int lane = tid & 31;
    const int b    = blockIdx.z;
    const int h    = blockIdx.y;
    const int bh   = b * NH + h;
    const int q0   = blockIdx.x * 8;
    const float scale = 0.125f;  // 1/sqrt(64)

    // stage 8 query rows
    for (int i = tid; i < 8 * 64; i += 256)
        qrow[i >> 6][i & 63] = g_Q[((size_t)(bh*SEQ + q0 + (i >> 6))) * HD + (i & 63)];
    __syncthreads();

    const float* Kbase = g_K + (size_t)bh * SEQ * HD;
    const float* Vbase = g_V + (size_t)bh * SEQ * HD;

    float sc[64];

    // ---- scores: Q @ K^T * scale ----
    #pragma unroll
    for (int kt = 0; kt < 32; kt++) {
        const float4* Kb4 = (const float4*)(Kbase + (size_t)(kt * 64) * HD);
        for (int i = tid; i < 1024; i += 256) {           // 64 keys x 16 float4
            const int key = i >> 4, d4 = i & 15;
            ((float4*)&tile[key][0])[d4] = Kb4[key * 16 + d4];
        }
        __syncthreads();
        float s0 = 0.f, s1 = 0.f;
        const float4* qp  = (const float4*)&qrow[w][0];
        const float4* k0p = (const float4*)&tile[lane][0];
        const float4* k1p = (const float4*)&tile[lane + 32][0];
        #pragma unroll
        for (int d4 = 0; d4 < 16; d4++) {
            float4 qv = qp[d4];
            float4 ka = k0p[d4];
            float4 kb = k1p[d4];
            s0 += qv.x*ka.x + qv.y*ka.y + qv.z*ka.z + qv.w*ka.w;
            s1 += qv.x*kb.x + qv.y*kb.y + qv.z*kb.z + qv.w*kb.w;
        }
        sc[2*kt]     = s0 * scale;
        sc[2*kt + 1] = s1 * scale;
        __syncthreads();
    }

    // ---- softmax across the 64 regs + warp ----
    float mx = -1e30f;
    #pragma unroll
    for (int j = 0; j < 64; j++) mx = fmaxf(mx, sc[j]);
    #pragma unroll
    for (int o = 16; o >= 1; o >>= 1)
        mx = fmaxf(mx, __shfl_xor_sync(0xffffffffu, mx, o));
    float sum = 0.f;
    #pragma unroll
    for (int j = 0; j < 64; j++) { sc[j] = __expf(sc[j] - mx); sum += sc[j]; }
    #pragma unroll
    for (int o = 16; o >= 1; o >>= 1)
        sum += __shfl_xor_sync(0xffffffffu, sum, o);
    const float inv = 1.f / sum;
    #pragma unroll
    for (int j = 0; j < 64; j++) sc[j] *= inv;

    // ---- write probs [b,h,q,k] (coalesced) ----
    float* prob_row = probs_out + ((size_t)(bh * SEQ + q0 + w)) * SEQ;
    #pragma unroll
    for (int kt = 0; kt < 32; kt++) {
        prob_row[kt*64 + lane]      = sc[2*kt];
        prob_row[kt*64 + 32 + lane] = sc[2*kt + 1];
    }

    // ---- ctx = probs @ V ----
    float acc0 = 0.f, acc1 = 0.f;
    #pragma unroll
    for (int kt = 0; kt < 32; kt++) {
        __syncthreads();   // previous tile fully consumed
        const float4* Vb4 = (const float4*)(Vbase + (size_t)(kt * 64) * HD);
        for (int i = tid; i < 1024; i += 256) {
            const int key = i >> 4, d4 = i & 15;
            ((float4*)&tile[key][0])[d4] = Vb4[key * 16 + d4];
        }
        prow[w][lane]      = sc[2*kt];
        prow[w][lane + 32] = sc[2*kt + 1];
        __syncthreads();
        #pragma unroll
        for (int key = 0; key < 64; key++) {
            const float p = prow[w][key];
            acc0 += p * tile[key][lane];
            acc1 += p * tile[key][lane + 32];
        }
    }

    // ctx layout: [b, s, h*64 + d]
    float* crow = ctx_out + ((size_t)(b * SEQ + q0 + w)) * HID + h * HD;
    crow[lane]      = acc0;
    crow[lane + 32] = acc1;
}

// ---------------------------------------------------------------------------
extern "C" void kernel_launch(void* const* d_in, const int* in_sizes, int n_in,
                              void* d_out, int out_size)
{
    const float* X  = (const float*)d_in[0];
    const float* Wq = (const float*)d_in[1];
    const float* bq = (const float*)d_in[2];
    const float* Wk = (const float*)d_in[3];
    const float* bk = (const float*)d_in[4];
    const float* Wv = (const float*)d_in[5];
    const float* bv = (const float*)d_in[6];

    float* ctx   = (float*)d_out;                               // 2*2048*1024
    float* probs = (float*)d_out + (size_t)BATCH * SEQ * HID;   // 2*16*2048*2048

    dim3 gemm_grid(HID / 128, MTOT / 128, 3);
    qkv_gemm_kernel<<<gemm_grid, 256>>>(X, Wq, bq, Wk, bk, Wv, bv);

    dim3 attn_grid(SEQ / 8, NH, BATCH);
    attn_kernel<<<attn_grid, 256>>>(ctx, probs);
}

// round 3
// speedup vs baseline: 2.1227x; 2.1227x over previous
#include <cuda_runtime.h>
#include <cstddef>

#define HID   1024
#define NH    16
#define HD    64
#define BATCH 2
#define SEQ   2048
#define BH    (BATCH*NH)       /* 32  */
#define MTOT  (BATCH*SEQ)      /* 4096 */

// Scratch for projected Q,K,V in [b,h,s,d] layout (16 MB each).
__device__ float g_Q[(size_t)BH*SEQ*HD];
__device__ float g_K[(size_t)BH*SEQ*HD];
__device__ float g_V[(size_t)BH*SEQ*HD];

// ---------------------------------------------------------------------------
// QKV projection: Y = X @ W^T + b, written into [b,h,s,d] scratch.
// 128x128 tile, BK=8, 256 threads, 8x8 microtile. (unchanged from R1 — FMA bound)
// ---------------------------------------------------------------------------
__global__ __launch_bounds__(256) void qkv_gemm_kernel(
    const float* __restrict__ X,
    const float* __restrict__ Wq, const float* __restrict__ bq,
    const float* __restrict__ Wk, const float* __restrict__ bk,
    const float* __restrict__ Wv, const float* __restrict__ bv)
{
    const float* W; const float* bias; float* out;
    if (blockIdx.z == 0)      { W = Wq; bias = bq; out = g_Q; }
    else if (blockIdx.z == 1) { W = Wk; bias = bk; out = g_K; }
    else                      { W = Wv; bias = bv; out = g_V; }

    __shared__ float As[8][128];
    __shared__ float Bs[8][128];

    const int tid  = threadIdx.x;
    const int tx   = tid & 15;
    const int ty   = tid >> 4;
    const int lrow = tid >> 1;
    const int lk   = (tid & 1) * 4;

    const float* Xb = X + (size_t)(blockIdx.y * 128) * HID;
    const float* Wb = W + (size_t)(blockIdx.x * 128) * HID;

    float acc[8][8];
    #pragma unroll
    for (int i = 0; i < 8; i++)
        #pragma unroll
        for (int j = 0; j < 8; j++) acc[i][j] = 0.f;

    for (int k0 = 0; k0 < HID; k0 += 8) {
        float4 xa = *(const float4*)(Xb + (size_t)lrow * HID + k0 + lk);
        float4 wa = *(const float4*)(Wb + (size_t)lrow * HID + k0 + lk);
        __syncthreads();
        As[lk+0][lrow] = xa.x; As[lk+1][lrow] = xa.y;
        As[lk+2][lrow] = xa.z; As[lk+3][lrow] = xa.w;
        Bs[lk+0][lrow] = wa.x; Bs[lk+1][lrow] = wa.y;
        Bs[lk+2][lrow] = wa.z; Bs[lk+3][lrow] = wa.w;
        __syncthreads();
        #pragma unroll
        for (int k = 0; k < 8; k++) {
            float a[8], b[8];
            #pragma unroll
            for (int i = 0; i < 8; i++) a[i] = As[k][ty*8 + i];
            #pragma unroll
            for (int j = 0; j < 8; j++) b[j] = Bs[k][tx*8 + j];
            #pragma unroll
            for (int i = 0; i < 8; i++)
                #pragma unroll
                for (int j = 0; j < 8; j++) acc[i][j] += a[i] * b[j];
        }
    }

    #pragma unroll
    for (int i = 0; i < 8; i++) {
        const int m  = blockIdx.y * 128 + ty*8 + i;
        const int bb = m >> 11;
        const int s  = m & (SEQ - 1);
        #pragma unroll
        for (int j = 0; j < 8; j++) {
            const int n = blockIdx.x * 128 + tx*8 + j;
            const int h = n >> 6;
            const int d = n & 63;
            out[(((size_t)(bb*NH + h) * SEQ) + s) * HD + d] = acc[i][j] + bias[n];
        }
    }
}

// ---------------------------------------------------------------------------
// Fused attention, GEMM-structured.
// Block: 256 threads, 32 queries x all 2048 keys of one (b,h).
// Phase 1: scores GEMM (4q x 4k microtile), raw scaled scores -> probs buffer,
//          online row (max,sum) in registers.
// Phase 2: re-read scores (L2-hot), exp-normalize, write final probs, and
//          P@V GEMM (2q x 4d microtile) -> ctx.
// ---------------------------------------------------------------------------
__global__ __launch_bounds__(256) void attn_kernel(
    float* __restrict__ ctx_out, float* probs_out)
{
    __shared__ __align__(16) float sm[10496];   // 41 KB, phase-unioned
    float* sQ = sm;              // [64][32]    phase 1 (2048 floats)
    float* sK = sm + 2048;       // [64][132]   phase 1 (8448 floats)
    float* sStats = sm;          // [64]        phase 2 (m, inv)
    float* sP = sm + 64;         // [64][34]    phase 2 (2176 floats)
    float* sV = sm + 2240;       // [64][68]    phase 2 (4352 floats)

    const int tid  = threadIdx.x;
    const int lane = tid & 31;
    const int w    = tid >> 5;
    const int bh   = blockIdx.y;          // 0..31
    const int b    = bh >> 4;
    const int h    = bh & 15;
    const int q0   = blockIdx.x * 32;
    const float scale = 0.125f;

    const float* Qbase = g_Q + ((size_t)bh * SEQ + q0) * HD;
    const float* Kbase = g_K + (size_t)bh * SEQ * HD;
    const float* Vbase = g_V + (size_t)bh * SEQ * HD;
    float* Sbuf = probs_out + ((size_t)bh * SEQ + q0) * SEQ;  // this block's 32 rows

    // ---- stage Q transposed: sQ[d][q] ----
    {
        const int q  = tid & 31;
        #pragma unroll
        for (int pass = 0; pass < 2; pass++) {
            const int d4 = (tid >> 5) + pass * 8;   // 0..15
            float4 v = *(const float4*)(Qbase + (size_t)q * HD + d4 * 4);
            sQ[(d4*4+0)*32 + q] = v.x;
            sQ[(d4*4+1)*32 + q] = v.y;
            sQ[(d4*4+2)*32 + q] = v.z;
            sQ[(d4*4+3)*32 + q] = v.w;
        }
    }

    float m[4], s[4];
    #pragma unroll
    for (int i = 0; i < 4; i++) { m[i] = -1e30f; s[i] = 0.f; }

    // =================== Phase 1: scores + online softmax stats ===========
    for (int kt = 0; kt < 16; kt++) {
        __syncthreads();
        // stage K tile transposed: sK[d][key], 128 keys
        const float* Kb = Kbase + (size_t)(kt * 128) * HD;
        #pragma unroll
        for (int kb = 0; kb < 4; kb++) {
            #pragma unroll
            for (int dh = 0; dh < 2; dh++) {
                const int key = kb*32 + (tid >> 3);
                const int d4  = (tid & 7) + dh*8;
                float4 v = *(const float4*)(Kb + (size_t)key * HD + d4 * 4);
                sK[(d4*4+0)*132 + key] = v.x;
                sK[(d4*4+1)*132 + key] = v.y;
                sK[(d4*4+2)*132 + key] = v.z;
                sK[(d4*4+3)*132 + key] = v.w;
            }
        }
        __syncthreads();

        float acc[4][4];
        #pragma unroll
        for (int i = 0; i < 4; i++)
            #pragma unroll
            for (int j = 0; j < 4; j++) acc[i][j] = 0.f;

        #pragma unroll 8
        for (int d = 0; d < 64; d++) {
            float4 a = *(const float4*)&sQ[d*32 + w*4];       // broadcast
            float4 bv = *(const float4*)&sK[d*132 + lane*4];
            float av[4] = {a.x, a.y, a.z, a.w};
            float bb[4] = {bv.x, bv.y, bv.z, bv.w};
            #pragma unroll
            for (int i = 0; i < 4; i++)
                #pragma unroll
                for (int j = 0; j < 4; j++) acc[i][j] += av[i] * bb[j];
        }

        #pragma unroll
        for (int i = 0; i < 4; i++) {
            float v0 = acc[i][0]*scale, v1 = acc[i][1]*scale;
            float v2 = acc[i][2]*scale, v3 = acc[i][3]*scale;
            float4 st = {v0, v1, v2, v3};
            *(float4*)(Sbuf + (size_t)(w*4+i)*SEQ + kt*128 + lane*4) = st;
            float tmax = fmaxf(fmaxf(v0,v1), fmaxf(v2,v3));
            #pragma unroll
            for (int o = 16; o >= 1; o >>= 1)
                tmax = fmaxf(tmax, __shfl_xor_sync(0xffffffffu, tmax, o));
            const float mnew = fmaxf(m[i], tmax);
            float ts = __expf(v0-mnew) + __expf(v1-mnew) + __expf(v2-mnew) + __expf(v3-mnew);
            #pragma unroll
            for (int o = 16; o >= 1; o >>= 1)
                ts += __shfl_xor_sync(0xffffffffu, ts, o);
            s[i] = s[i] * __expf(m[i] - mnew) + ts;
            m[i] = mnew;
        }
    }

    // publish stats (overlaps sQ region — safe after sync)
    __syncthreads();
    if (lane == 0) {
        #pragma unroll
        for (int i = 0; i < 4; i++) {
            sStats[w*4+i]      = m[i];
            sStats[32 + w*4+i] = 1.f / s[i];
        }
    }
    __syncthreads();

    // =================== Phase 2: normalize probs + P@V ====================
    const int dy = tid & 15;    // d group: d = dy*4
    const int qx = tid >> 4;    // q pair: rows qx*2, qx*2+1
    float acc2[2][4];
    #pragma unroll
    for (int r = 0; r < 2; r++)
        #pragma unroll
        for (int j = 0; j < 4; j++) acc2[r][j] = 0.f;

    const int halfl = lane >> 4;   // 0/1
    const int k4    = lane & 15;   // float4 index within 64 keys

    for (int kt = 0; kt < 32; kt++) {
        __syncthreads();
        // stage P tile (exp-normalized) transposed: sP[k][q], and final probs write
        #pragma unroll
        for (int rr = 0; rr < 2; rr++) {
            const int q = w*4 + rr*2 + halfl;
            const float m_   = sStats[q];
            const float inv_ = sStats[32 + q];
            float* gp = Sbuf + (size_t)q*SEQ + kt*64 + k4*4;
            float4 sv = *(const float4*)gp;
            float4 pv = { __expf(sv.x - m_) * inv_,
                          __expf(sv.y - m_) * inv_,
                          __expf(sv.z - m_) * inv_,
                          __expf(sv.w - m_) * inv_ };
            *(float4*)gp = pv;
            const int k = k4*4;
            sP[(k+0)*34 + q] = pv.x;
            sP[(k+1)*34 + q] = pv.y;
            sP[(k+2)*34 + q] = pv.z;
            sP[(k+3)*34 + q] = pv.w;
        }
        // stage V tile: sV[key][d]
        const float* Vb = Vbase + (size_t)(kt * 64) * HD;
        #pragma unroll
        for (int p = 0; p < 4; p++) {
            const int idx = p*256 + tid;
            const int key = idx >> 4, d4 = idx & 15;
            float4 v = *(const float4*)(Vb + (size_t)key * HD + d4 * 4);
            *(float4*)&sV[key*68 + d4*4] = v;
        }
        __syncthreads();

        #pragma unroll 8
        for (int k = 0; k < 64; k++) {
            float2 p  = *(const float2*)&sP[k*34 + qx*2];
            float4 vv = *(const float4*)&sV[k*68 + dy*4];
            acc2[0][0] += p.x * vv.x; acc2[0][1] += p.x * vv.y;
            acc2[0][2] += p.x * vv.z; acc2[0][3] += p.x * vv.w;
            acc2[1][0] += p.y * vv.x; acc2[1][1] += p.y * vv.y;
            acc2[1][2] += p.y * vv.z; acc2[1][3] += p.y * vv.w;
        }
    }

    // ctx layout: [b, s, h*64 + d]
    #pragma unroll
    for (int r = 0; r < 2; r++) {
        float* crow = ctx_out + ((size_t)(b*SEQ + q0 + qx*2 + r)) * HID + h*HD + dy*4;
        float4 o = {acc2[r][0], acc2[r][1], acc2[r][2], acc2[r][3]};
        *(float4*)crow = o;
    }
}

// ---------------------------------------------------------------------------
extern "C" void kernel_launch(void* const* d_in, const int* in_sizes, int n_in,
                              void* d_out, int out_size)
{
    const float* X  = (const float*)d_in[0];
    const float* Wq = (const float*)d_in[1];
    const float* bq = (const float*)d_in[2];
    const float* Wk = (const float*)d_in[3];
    const float* bk = (const float*)d_in[4];
    const float* Wv = (const float*)d_in[5];
    const float* bv = (const float*)d_in[6];

    float* ctx   = (float*)d_out;                               // 2*2048*1024
    float* probs = (float*)d_out + (size_t)BATCH * SEQ * HID;   // 2*16*2048*2048

    dim3 gemm_grid(HID / 128, MTOT / 128, 3);
    qkv_gemm_kernel<<<gemm_grid, 256>>>(X, Wq, bq, Wk, bk, Wv, bv);

    dim3 attn_grid(SEQ / 32, BH);
    attn_kernel<<<attn_grid, 256>>>(ctx, probs);
}

// round 4
// speedup vs baseline: 2.1261x; 1.0016x over previous
#include <cuda_runtime.h>
#include <cstddef>

#define HID   1024
#define NH    16
#define HD    64
#define BATCH 2
#define SEQ   2048
#define BH    (BATCH*NH)       /* 32  */
#define MTOT  (BATCH*SEQ)      /* 4096 */

// Scratch for projected Q,K,V in [b,h,s,d] layout (16 MB each).
__device__ float g_Q[(size_t)BH*SEQ*HD];
__device__ float g_K[(size_t)BH*SEQ*HD];
__device__ float g_V[(size_t)BH*SEQ*HD];

// ---------------------------------------------------------------------------
// QKV projection: Y = X @ W^T + b, written into [b,h,s,d] scratch.
// 128x128 tile, BK=8, 256 threads, 8x8 microtile. (unchanged from R1 — FMA bound)
// ---------------------------------------------------------------------------
__global__ __launch_bounds__(256) void qkv_gemm_kernel(
    const float* __restrict__ X,
    const float* __restrict__ Wq, const float* __restrict__ bq,
    const float* __restrict__ Wk, const float* __restrict__ bk,
    const float* __restrict__ Wv, const float* __restrict__ bv)
{
    const float* W; const float* bias; float* out;
    if (blockIdx.z == 0)      { W = Wq; bias = bq; out = g_Q; }
    else if (blockIdx.z == 1) { W = Wk; bias = bk; out = g_K; }
    else                      { W = Wv; bias = bv; out = g_V; }

    __shared__ float As[8][128];
    __shared__ float Bs[8][128];

    const int tid  = threadIdx.x;
    const int tx   = tid & 15;
    const int ty   = tid >> 4;
    const int lrow = tid >> 1;
    const int lk   = (tid & 1) * 4;

    const float* Xb = X + (size_t)(blockIdx.y * 128) * HID;
    const float* Wb = W + (size_t)(blockIdx.x * 128) * HID;

    float acc[8][8];
    #pragma unroll
    for (int i = 0; i < 8; i++)
        #pragma unroll
        for (int j = 0; j < 8; j++) acc[i][j] = 0.f;

    for (int k0 = 0; k0 < HID; k0 += 8) {
        float4 xa = *(const float4*)(Xb + (size_t)lrow * HID + k0 + lk);
        float4 wa = *(const float4*)(Wb + (size_t)lrow * HID + k0 + lk);
        __syncthreads();
        As[lk+0][lrow] = xa.x; As[lk+1][lrow] = xa.y;
        As[lk+2][lrow] = xa.z; As[lk+3][lrow] = xa.w;
        Bs[lk+0][lrow] = wa.x; Bs[lk+1][lrow] = wa.y;
        Bs[lk+2][lrow] = wa.z; Bs[lk+3][lrow] = wa.w;
        __syncthreads();
        #pragma unroll
        for (int k = 0; k < 8; k++) {
            float a[8], b[8];
            #pragma unroll
            for (int i = 0; i < 8; i++) a[i] = As[k][ty*8 + i];
            #pragma unroll
            for (int j = 0; j < 8; j++) b[j] = Bs[k][tx*8 + j];
            #pragma unroll
            for (int i = 0; i < 8; i++)
                #pragma unroll
                for (int j = 0; j < 8; j++) acc[i][j] += a[i] * b[j];
        }
    }

    #pragma unroll
    for (int i = 0; i < 8; i++) {
        const int m  = blockIdx.y * 128 + ty*8 + i;
        const int bb = m >> 11;
        const int s  = m & (SEQ - 1);
        #pragma unroll
        for (int j = 0; j < 8; j++) {
            const int n = blockIdx.x * 128 + tx*8 + j;
            const int h = n >> 6;
            const int d = n & 63;
            out[(((size_t)(bb*NH + h) * SEQ) + s) * HD + d] = acc[i][j] + bias[n];
        }
    }
}

// ---------------------------------------------------------------------------
// Fused attention, GEMM-structured.
// Block: 256 threads, 32 queries x all 2048 keys of one (b,h).
// Phase 1: scores GEMM (4q x 4k microtile), raw scaled scores -> probs buffer,
//          online row (max,sum) in registers.
// Phase 2: re-read scores (L2-hot), exp-normalize, write final probs, and
//          P@V GEMM (2q x 4d microtile) -> ctx.
// ---------------------------------------------------------------------------
__global__ __launch_bounds__(256) void attn_kernel(
    float* __restrict__ ctx_out, float* probs_out)
{
    __shared__ __align__(16) float sm[10496];   // 41 KB, phase-unioned
    float* sQ = sm;              // [64][32]    phase 1 (2048 floats)
    float* sK = sm + 2048;       // [64][132]   phase 1 (8448 floats)
    float* sStats = sm;          // [64]        phase 2 (m, inv)
    float* sP = sm + 64;         // [64][34]    phase 2 (2176 floats)
    float* sV = sm + 2240;       // [64][68]    phase 2 (4352 floats)

    const int tid  = threadIdx.x;
    const int lane = tid & 31;
    const int w    = tid >> 5;
    const int bh   = blockIdx.y;          // 0..31
    const int b    = bh >> 4;
    const int h    = bh & 15;
    const int q0   = blockIdx.x * 32;
    const float scale = 0.125f;

    const float* Qbase = g_Q + ((size_t)bh * SEQ + q0) * HD;
    const float* Kbase = g_K + (size_t)bh * SEQ * HD;
    const float* Vbase = g_V + (size_t)bh * SEQ * HD;
    float* Sbuf = probs_out + ((size_t)bh * SEQ + q0) * SEQ;  // this block's 32 rows

    // ---- stage Q transposed: sQ[d][q] ----
    {
        const int q  = tid & 31;
        #pragma unroll
        for (int pass = 0; pass < 2; pass++) {
            const int d4 = (tid >> 5) + pass * 8;   // 0..15
            float4 v = *(const float4*)(Qbase + (size_t)q * HD + d4 * 4);
            sQ[(d4*4+0)*32 + q] = v.x;
            sQ[(d4*4+1)*32 + q] = v.y;
            sQ[(d4*4+2)*32 + q] = v.z;
            sQ[(d4*4+3)*32 + q] = v.w;
        }
    }

    float m[4], s[4];
    #pragma unroll
    for (int i = 0; i < 4; i++) { m[i] = -1e30f; s[i] = 0.f; }

    // =================== Phase 1: scores + online softmax stats ===========
    for (int kt = 0; kt < 16; kt++) {
        __syncthreads();
        // stage K tile transposed: sK[d][key], 128 keys
        const float* Kb = Kbase + (size_t)(kt * 128) * HD;
        #pragma unroll
        for (int kb = 0; kb < 4; kb++) {
            #pragma unroll
            for (int dh = 0; dh < 2; dh++) {
                const int key = kb*32 + (tid >> 3);
                const int d4  = (tid & 7) + dh*8;
                float4 v = *(const float4*)(Kb + (size_t)key * HD + d4 * 4);
                sK[(d4*4+0)*132 + key] = v.x;
                sK[(d4*4+1)*132 + key] = v.y;
                sK[(d4*4+2)*132 + key] = v.z;
                sK[(d4*4+3)*132 + key] = v.w;
            }
        }
        __syncthreads();

        float acc[4][4];
        #pragma unroll
        for (int i = 0; i < 4; i++)
            #pragma unroll
            for (int j = 0; j < 4; j++) acc[i][j] = 0.f;

        #pragma unroll 8
        for (int d = 0; d < 64; d++) {
            float4 a = *(const float4*)&sQ[d*32 + w*4];       // broadcast
            float4 bv = *(const float4*)&sK[d*132 + lane*4];
            float av[4] = {a.x, a.y, a.z, a.w};
            float bb[4] = {bv.x, bv.y, bv.z, bv.w};
            #pragma unroll
            for (int i = 0; i < 4; i++)
                #pragma unroll
                for (int j = 0; j < 4; j++) acc[i][j] += av[i] * bb[j];
        }

        #pragma unroll
        for (int i = 0; i < 4; i++) {
            float v0 = acc[i][0]*scale, v1 = acc[i][1]*scale;
            float v2 = acc[i][2]*scale, v3 = acc[i][3]*scale;
            float4 st = {v0, v1, v2, v3};
            *(float4*)(Sbuf + (size_t)(w*4+i)*SEQ + kt*128 + lane*4) = st;
            float tmax = fmaxf(fmaxf(v0,v1), fmaxf(v2,v3));
            #pragma unroll
            for (int o = 16; o >= 1; o >>= 1)
                tmax = fmaxf(tmax, __shfl_xor_sync(0xffffffffu, tmax, o));
            const float mnew = fmaxf(m[i], tmax);
            float ts = __expf(v0-mnew) + __expf(v1-mnew) + __expf(v2-mnew) + __expf(v3-mnew);
            #pragma unroll
            for (int o = 16; o >= 1; o >>= 1)
                ts += __shfl_xor_sync(0xffffffffu, ts, o);
            s[i] = s[i] * __expf(m[i] - mnew) + ts;
            m[i] = mnew;
        }
    }

    // publish stats (overlaps sQ region — safe after sync)
    __syncthreads();
    if (lane == 0) {
        #pragma unroll
        for (int i = 0; i < 4; i++) {
            sStats[w*4+i]      = m[i];
            sStats[32 + w*4+i] = 1.f / s[i];
        }
    }
    __syncthreads();

    // =================== Phase 2: normalize probs + P@V ====================
    const int dy = tid & 15;    // d group: d = dy*4
    const int qx = tid >> 4;    // q pair: rows qx*2, qx*2+1
    float acc2[2][4];
    #pragma unroll
    for (int r = 0; r < 2; r++)
        #pragma unroll
        for (int j = 0; j < 4; j++) acc2[r][j] = 0.f;

    const int halfl = lane >> 4;   // 0/1
    const int k4    = lane & 15;   // float4 index within 64 keys

    for (int kt = 0; kt < 32; kt++) {
        __syncthreads();
        // stage P tile (exp-normalized) transposed: sP[k][q], and final probs write
        #pragma unroll
        for (int rr = 0; rr < 2; rr++) {
            const int q = w*4 + rr*2 + halfl;
            const float m_   = sStats[q];
            const float inv_ = sStats[32 + q];
            float* gp = Sbuf + (size_t)q*SEQ + kt*64 + k4*4;
            float4 sv = *(const float4*)gp;
            float4 pv = { __expf(sv.x - m_) * inv_,
                          __expf(sv.y - m_) * inv_,
                          __expf(sv.z - m_) * inv_,
                          __expf(sv.w - m_) * inv_ };
            *(float4*)gp = pv;
            const int k = k4*4;
            sP[(k+0)*34 + q] = pv.x;
            sP[(k+1)*34 + q] = pv.y;
            sP[(k+2)*34 + q] = pv.z;
            sP[(k+3)*34 + q] = pv.w;
        }
        // stage V tile: sV[key][d]
        const float* Vb = Vbase + (size_t)(kt * 64) * HD;
        #pragma unroll
        for (int p = 0; p < 4; p++) {
            const int idx = p*256 + tid;
            const int key = idx >> 4, d4 = idx & 15;
            float4 v = *(const float4*)(Vb + (size_t)key * HD + d4 * 4);
            *(float4*)&sV[key*68 + d4*4] = v;
        }
        __syncthreads();

        #pragma unroll 8
        for (int k = 0; k < 64; k++) {
            float2 p  = *(const float2*)&sP[k*34 + qx*2];
            float4 vv = *(const float4*)&sV[k*68 + dy*4];
            acc2[0][0] += p.x * vv.x; acc2[0][1] += p.x * vv.y;
            acc2[0][2] += p.x * vv.z; acc2[0][3] += p.x * vv.w;
            acc2[1][0] += p.y * vv.x; acc2[1][1] += p.y * vv.y;
            acc2[1][2] += p.y * vv.z; acc2[1][3] += p.y * vv.w;
        }
    }

    // ctx layout: [b, s, h*64 + d]
    #pragma unroll
    for (int r = 0; r < 2; r++) {
        float* crow = ctx_out + ((size_t)(b*SEQ + q0 + qx*2 + r)) * HID + h*HD + dy*4;
        float4 o = {acc2[r][0], acc2[r][1], acc2[r][2], acc2[r][3]};
        *(float4*)crow = o;
    }
}

// ---------------------------------------------------------------------------
extern "C" void kernel_launch(void* const* d_in, const int* in_sizes, int n_in,
                              void* d_out, int out_size)
{
    const float* X  = (const float*)d_in[0];
    const float* Wq = (const float*)d_in[1];
    const float* bq = (const float*)d_in[2];
    const float* Wk = (const float*)d_in[3];
    const float* bk = (const float*)d_in[4];
    const float* Wv = (const float*)d_in[5];
    const float* bv = (const float*)d_in[6];

    float* ctx   = (float*)d_out;                               // 2*2048*1024
    float* probs = (float*)d_out + (size_t)BATCH * SEQ * HID;   // 2*16*2048*2048

    dim3 gemm_grid(HID / 128, MTOT / 128, 3);
    qkv_gemm_kernel<<<gemm_grid, 256>>>(X, Wq, bq, Wk, bk, Wv, bv);

    dim3 attn_grid(SEQ / 32, BH);
    attn_kernel<<<attn_grid, 256>>>(ctx, probs);
}

// round 6
// speedup vs baseline: 5.3127x; 2.4988x over previous
#include <cuda_runtime.h>
#include <cuda_bf16.h>
#include <cstdint>
#include <cstddef>

#define HID   1024
#define NH    16
#define HD    64
#define BATCH 2
#define SEQ   2048
#define BH    (BATCH*NH)
#define MTOT  (BATCH*SEQ)

// packed split-bf16: low 16 bits = hi part, high 16 bits = lo part
__device__ __align__(16) uint32_t g_Xs[(size_t)MTOT * HID];
__device__ __align__(16) uint32_t g_Ws[3][(size_t)HID * HID];
__device__ __align__(16) uint32_t g_QKV[3][(size_t)BH * SEQ * HD];
__device__ __align__(16) float2   g_stats[(size_t)BH * SEQ];    // {rowmax, 1/rowsum}

__device__ __forceinline__ uint32_t packsplit(float x) {
    __nv_bfloat16 h = __float2bfloat16(x);
    __nv_bfloat16 l = __float2bfloat16(x - __bfloat162float(h));
    return (uint32_t)__bfloat16_as_ushort(h) | ((uint32_t)__bfloat16_as_ushort(l) << 16);
}
__device__ __forceinline__ void mma_bf16(float* d, const uint32_t* a, const uint32_t* b) {
    asm volatile("mma.sync.aligned.m16n8k16.row.col.f32.bf16.bf16.f32 "
        "{%0,%1,%2,%3}, {%4,%5,%6,%7}, {%8,%9}, {%0,%1,%2,%3};\n"
        : "+f"(d[0]), "+f"(d[1]), "+f"(d[2]), "+f"(d[3])
        : "r"(a[0]), "r"(a[1]), "r"(a[2]), "r"(a[3]), "r"(b[0]), "r"(b[1]));
}
__device__ __forceinline__ void ldsm_x4(uint32_t* r, uint32_t a) {
    asm volatile("ldmatrix.sync.aligned.m8n8.x4.shared.b16 {%0,%1,%2,%3}, [%4];\n"
                 : "=r"(r[0]), "=r"(r[1]), "=r"(r[2]), "=r"(r[3]) : "r"(a));
}
__device__ __forceinline__ void ldsm_x4_t(uint32_t* r, uint32_t a) {
    asm volatile("ldmatrix.sync.aligned.m8n8.x4.trans.shared.b16 {%0,%1,%2,%3}, [%4];\n"
                 : "=r"(r[0]), "=r"(r[1]), "=r"(r[2]), "=r"(r[3]) : "r"(a));
}
// stage 4 consecutive packed words -> hi/lo smem (row stride 36 words)
__device__ __forceinline__ void stage4(uint32_t* sh, uint32_t* sl, int row, int q4,
                                       const uint32_t* gp) {
    uint4 p = *(const uint4*)gp;
    uint2 hw = { __byte_perm(p.x, p.y, 0x5410), __byte_perm(p.z, p.w, 0x5410) };
    uint2 lw = { __byte_perm(p.x, p.y, 0x7632), __byte_perm(p.z, p.w, 0x7632) };
    *(uint2*)&sh[row*36 + q4*2] = hw;
    *(uint2*)&sl[row*36 + q4*2] = lw;
}

// ---------------- fp32 -> packed split-bf16 ---------------------------------
__global__ __launch_bounds__(256) void split_kernel(
    const float* __restrict__ src, uint32_t* __restrict__ dst, int n4)
{
    int i = blockIdx.x * 256 + threadIdx.x;
    if (i < n4) {
        float4 v = ((const float4*)src)[i];
        uint4 o = { packsplit(v.x), packsplit(v.y), packsplit(v.z), packsplit(v.w) };
        ((uint4*)dst)[i] = o;
    }
}

// ---------------- QKV GEMM (tensor), Y = X W^T + b; Q scaled by 1/8 ---------
__global__ __launch_bounds__(256) void qkv_t_kernel(
    const float* __restrict__ bq, const float* __restrict__ bk, const float* __restrict__ bv)
{
    __shared__ __align__(16) uint32_t sXh[64*36], sXl[64*36], sWh[64*36], sWl[64*36];
    __shared__ float sBias[64];
    const int tid = threadIdx.x, lane = tid & 31, wid = tid >> 5;
    const int z = blockIdx.z, n0 = blockIdx.x * 64, m0 = blockIdx.y * 64;
    const int wm = wid & 3, wn = wid >> 2;
    const uint32_t* Wg = g_Ws[z];
    const float* bias = (z == 0) ? bq : (z == 1) ? bk : bv;
    uint32_t* outp = g_QKV[z];
    if (tid < 64) sBias[tid] = bias[n0 + tid];

    const uint32_t XhB = (uint32_t)__cvta_generic_to_shared(sXh);
    const uint32_t XlB = (uint32_t)__cvta_generic_to_shared(sXl);
    const uint32_t WhB = (uint32_t)__cvta_generic_to_shared(sWh);
    const uint32_t WlB = (uint32_t)__cvta_generic_to_shared(sWl);

    float acc[4][4];
    #pragma unroll
    for (int s = 0; s < 4; s++) { acc[s][0]=acc[s][1]=acc[s][2]=acc[s][3]=0.f; }

    const uint32_t a_byte = (uint32_t)(wm*16 + (lane & 7) + ((lane >> 3) & 1)*8)*144
                          + ((lane >> 4) & 1)*16;
    const uint32_t b_row  = (uint32_t)(wn*32 + ((lane >> 4) & 1)*8 + (lane & 7));
    const uint32_t b_kofs = ((lane >> 3) & 1)*16;

    for (int k0 = 0; k0 < HID; k0 += 64) {
        __syncthreads();
        #pragma unroll
        for (int i = 0; i < 4; i++) {
            int idx = tid + i*256, row = idx >> 4, q4 = idx & 15;
            stage4(sXh, sXl, row, q4, g_Xs + (size_t)(m0+row)*HID + k0 + q4*4);
            stage4(sWh, sWl, row, q4, Wg   + (size_t)(n0+row)*HID + k0 + q4*4);
        }
        __syncthreads();
        #pragma unroll
        for (int kc = 0; kc < 4; kc++) {
            uint32_t Ah[4], Al[4];
            ldsm_x4(Ah, XhB + a_byte + kc*32);
            ldsm_x4(Al, XlB + a_byte + kc*32);
            #pragma unroll
            for (int sp = 0; sp < 2; sp++) {
                uint32_t Bh[4], Bl[4];
                uint32_t boff = (b_row + sp*16)*144 + b_kofs + kc*32;
                ldsm_x4(Bh, WhB + boff);
                ldsm_x4(Bl, WlB + boff);
                mma_bf16(acc[sp*2],   Ah, Bh);   mma_bf16(acc[sp*2],   Ah, Bl);
                mma_bf16(acc[sp*2],   Al, Bh);
                mma_bf16(acc[sp*2+1], Ah, Bh+2); mma_bf16(acc[sp*2+1], Ah, Bl+2);
                mma_bf16(acc[sp*2+1], Al, Bh+2);
            }
        }
    }
    const float qs = (z == 0) ? 0.125f : 1.0f;
    #pragma unroll
    for (int s = 0; s < 4; s++) {
        const int nl = wn*32 + s*8 + (lane & 3)*2, n = n0 + nl;
        const int h = n >> 6, d = n & 63;
        const float b0 = sBias[nl], b1 = sBias[nl+1];
        #pragma unroll
        for (int half = 0; half < 2; half++) {
            const int m = m0 + wm*16 + (lane >> 2) + half*8;
            const int bb = m >> 11, ss = m & (SEQ-1);
            uint2 w = { packsplit((acc[s][half*2]   + b0)*qs),
                        packsplit((acc[s][half*2+1] + b1)*qs) };
            *(uint2*)(outp + ((size_t)(bb*NH+h)*SEQ + ss)*HD + d) = w;
        }
    }
}

// ---------------- scores (tensor) + fused online row stats ------------------
__global__ __launch_bounds__(256) void scores_t_kernel(float* __restrict__ Sbuf_all)
{
    __shared__ __align__(16) uint32_t sbuf[9216];
    __shared__ float2 sMS[64][2];
    const int tid = threadIdx.x, lane = tid & 31, wid = tid >> 5;
    const int bh = blockIdx.y, q0 = blockIdx.x * 64;
    const int wq = wid & 3, wk = wid >> 2;
    const uint32_t* Qg = g_QKV[0] + ((size_t)bh*SEQ + q0)*HD;
    const uint32_t* Kg = g_QKV[1] + (size_t)bh*SEQ*HD;
    float* Sbuf = Sbuf_all + ((size_t)bh*SEQ + q0)*SEQ;

    const uint32_t base = (uint32_t)__cvta_generic_to_shared(sbuf);
    uint32_t* sQh = sbuf; uint32_t* sQl = sbuf + 2304;
    uint32_t* sKh = sbuf; uint32_t* sKl = sbuf + 4608;
    const uint32_t QhB = base, QlB = base + 2304*4, KhB = base, KlB = base + 4608*4;

    #pragma unroll
    for (int i = 0; i < 4; i++) {
        int idx = tid + i*256, row = idx >> 4, q4 = idx & 15;
        stage4(sQh, sQl, row, q4, Qg + (size_t)row*HD + q4*4);
    }
    __syncthreads();

    uint32_t Ah[4][4], Al[4][4];
    const uint32_t a_byte = (uint32_t)(wq*16 + (lane & 7) + ((lane >> 3) & 1)*8)*144
                          + ((lane >> 4) & 1)*16;
    #pragma unroll
    for (int kc = 0; kc < 4; kc++) { ldsm_x4(Ah[kc], QhB + a_byte + kc*32);
                                     ldsm_x4(Al[kc], QlB + a_byte + kc*32); }
    const uint32_t b_row  = (uint32_t)(((lane >> 4) & 1)*8 + (lane & 7));
    const uint32_t b_kofs = ((lane >> 3) & 1)*16;

    float m0r = -1e30f, s0r = 0.f, m1r = -1e30f, s1r = 0.f;

    for (int kt = 0; kt < 16; kt++) {
        __syncthreads();
        #pragma unroll
        for (int i = 0; i < 8; i++) {
            int idx = tid + i*256, row = idx >> 4, q4 = idx & 15;
            stage4(sKh, sKl, row, q4, Kg + (size_t)(kt*128 + row)*HD + q4*4);
        }
        __syncthreads();

        float acc[8][4];
        #pragma unroll
        for (int s = 0; s < 8; s++) { acc[s][0]=acc[s][1]=acc[s][2]=acc[s][3]=0.f; }
        #pragma unroll
        for (int kc = 0; kc < 4; kc++) {
            #pragma unroll
            for (int sp = 0; sp < 4; sp++) {
                uint32_t Bh[4], Bl[4];
                uint32_t boff = (uint32_t)(wk*64 + sp*16 + b_row)*144 + b_kofs + kc*32;
                ldsm_x4(Bh, KhB + boff);
                ldsm_x4(Bl, KlB + boff);
                mma_bf16(acc[sp*2],   Ah[kc], Bh);   mma_bf16(acc[sp*2],   Ah[kc], Bl);
                mma_bf16(acc[sp*2],   Al[kc], Bh);
                mma_bf16(acc[sp*2+1], Ah[kc], Bh+2); mma_bf16(acc[sp*2+1], Ah[kc], Bl+2);
                mma_bf16(acc[sp*2+1], Al[kc], Bh+2);
            }
        }
        // write raw scores (Q pre-scaled by 1/8)
        const int r0 = wq*16 + (lane >> 2);
        #pragma unroll
        for (int s = 0; s < 8; s++) {
            const int col = kt*128 + wk*64 + s*8 + (lane & 3)*2;
            *(float2*)(Sbuf + (size_t)r0*SEQ + col)     = make_float2(acc[s][0], acc[s][1]);
            *(float2*)(Sbuf + (size_t)(r0+8)*SEQ + col) = make_float2(acc[s][2], acc[s][3]);
        }
        // online stats for rows r0 and r0+8 (this warp's 64-col slice)
        float t0 = -1e30f, t1 = -1e30f;
        #pragma unroll
        for (int s = 0; s < 8; s++) {
            t0 = fmaxf(t0, fmaxf(acc[s][0], acc[s][1]));
            t1 = fmaxf(t1, fmaxf(acc[s][2], acc[s][3]));
        }
        t0 = fmaxf(t0, __shfl_xor_sync(0xffffffffu, t0, 1));
        t0 = fmaxf(t0, __shfl_xor_sync(0xffffffffu, t0, 2));
        t1 = fmaxf(t1, __shfl_xor_sync(0xffffffffu, t1, 1));
        t1 = fmaxf(t1, __shfl_xor_sync(0xffffffffu, t1, 2));
        const float mn0 = fmaxf(m0r, t0), mn1 = fmaxf(m1r, t1);
        float e0 = 0.f, e1 = 0.f;
        #pragma unroll
        for (int s = 0; s < 8; s++) {
            e0 += __expf(acc[s][0]-mn0) + __expf(acc[s][1]-mn0);
            e1 += __expf(acc[s][2]-mn1) + __expf(acc[s][3]-mn1);
        }
        e0 += __shfl_xor_sync(0xffffffffu, e0, 1); e0 += __shfl_xor_sync(0xffffffffu, e0, 2);
        e1 += __shfl_xor_sync(0xffffffffu, e1, 1); e1 += __shfl_xor_sync(0xffffffffu, e1, 2);
        s0r = s0r * __expf(m0r - mn0) + e0; m0r = mn0;
        s1r = s1r * __expf(m1r - mn1) + e1; m1r = mn1;
    }
    // combine two wk-halves per row, write g_stats
    __syncthreads();
    if ((lane & 3) == 0) {
        const int r0 = wq*16 + (lane >> 2);
        sMS[r0][wk]     = make_float2(m0r, s0r);
        sMS[r0 + 8][wk] = make_float2(m1r, s1r);
    }
    __syncthreads();
    if (tid < 64) {
        float2 a = sMS[tid][0], b = sMS[tid][1];
        float m = fmaxf(a.x, b.x);
        float s = a.y * __expf(a.x - m) + b.y * __expf(b.x - m);
        g_stats[(size_t)bh*SEQ + q0 + tid] = make_float2(m, 1.f / s);
    }
}

// ---------------- P@V (tensor): normalize probs in-place + ctx --------------
__global__ __launch_bounds__(256) void pv_t_kernel(
    float* __restrict__ ctx_out, float* __restrict__ Sbuf_all)
{
    __shared__ __align__(16) uint32_t sbuf[9216];
    __shared__ float2 sStats[64];
    const int tid = threadIdx.x, lane = tid & 31, wid = tid >> 5;
    const int bh = blockIdx.y, b = bh >> 4, h = bh & 15;
    const int q0 = blockIdx.x * 64;
    const int wq = wid & 3, wd = wid >> 2;
    float* Sbuf = Sbuf_all + ((size_t)bh*SEQ + q0)*SEQ;
    const uint32_t* Vg = g_QKV[2] + (size_t)bh*SEQ*HD;
    if (tid < 64) sStats[tid] = g_stats[(size_t)bh*SEQ + q0 + tid];

    const uint32_t base = (uint32_t)__cvta_generic_to_shared(sbuf);
    uint32_t* sPh = sbuf;        uint32_t* sPl = sbuf + 2304;
    uint32_t* sVh = sbuf + 4608; uint32_t* sVl = sbuf + 6912;
    const uint32_t PhB = base, PlB = base + 2304*4, VhB = base + 4608*4, VlB = base + 6912*4;

    float acc[4][4];
    #pragma unroll
    for (int s = 0; s < 4; s++) { acc[s][0]=acc[s][1]=acc[s][2]=acc[s][3]=0.f; }

    const uint32_t a_byte = (uint32_t)(wq*16 + (lane & 7) + ((lane >> 3) & 1)*8)*144
                          + ((lane >> 4) & 1)*16;
    const uint32_t bt_row = (uint32_t)((lane & 7) + ((lane >> 3) & 1)*8);
    const uint32_t bt_col = ((lane >> 4) & 1)*8;

    for (int kt = 0; kt < 32; kt++) {
        __syncthreads();
        #pragma unroll
        for (int i = 0; i < 4; i++) {
            int idx = tid + i*256, row = idx >> 4, c4 = idx & 15;
            float* gp = Sbuf + (size_t)row*SEQ + kt*64 + c4*4;
            float4 v = *(const float4*)gp;
            const float2 st = sStats[row];
            float p0 = __expf(v.x - st.x) * st.y, p1 = __expf(v.y - st.x) * st.y;
            float p2 = __expf(v.z - st.x) * st.y, p3 = __expf(v.w - st.x) * st.y;
            *(float4*)gp = make_float4(p0, p1, p2, p3);
            uint32_t s0 = packsplit(p0), s1 = packsplit(p1);
            uint32_t s2 = packsplit(p2), s3 = packsplit(p3);
            uint2 hw = { __byte_perm(s0, s1, 0x5410), __byte_perm(s2, s3, 0x5410) };
            uint2 lw = { __byte_perm(s0, s1, 0x7632), __byte_perm(s2, s3, 0x7632) };
            *(uint2*)&sPh[row*36 + c4*2] = hw;
            *(uint2*)&sPl[row*36 + c4*2] = lw;
        }
        #pragma unroll
        for (int i = 0; i < 4; i++) {
            int idx = tid + i*256, row = idx >> 4, d4 = idx & 15;
            stage4(sVh, sVl, row, d4, Vg + (size_t)(kt*64 + row)*HD + d4*4);
        }
        __syncthreads();
        #pragma unroll
        for (int kc = 0; kc < 4; kc++) {
            uint32_t Ah[4], Al[4];
            ldsm_x4(Ah, PhB + a_byte + kc*32);
            ldsm_x4(Al, PlB + a_byte + kc*32);
            #pragma unroll
            for (int sp = 0; sp < 2; sp++) {
                uint32_t Bh[4], Bl[4];
                uint32_t boff = (uint32_t)(kc*16 + bt_row)*144
                              + (uint32_t)(wd*32 + sp*16 + bt_col)*2;
                ldsm_x4_t(Bh, VhB + boff);
                ldsm_x4_t(Bl, VlB + boff);
                mma_bf16(acc[sp*2],   Ah, Bh);   mma_bf16(acc[sp*2],   Ah, Bl);
                mma_bf16(acc[sp*2],   Al, Bh);
                mma_bf16(acc[sp*2+1], Ah, Bh+2); mma_bf16(acc[sp*2+1], Ah, Bl+2);
                mma_bf16(acc[sp*2+1], Al, Bh+2);
            }
        }
    }
    #pragma unroll
    for (int s = 0; s < 4; s++) {
        const int col = h*64 + wd*32 + s*8 + (lane & 3)*2;
        #pragma unroll
        for (int half = 0; half < 2; half++) {
            const int q = q0 + wq*16 + (lane >> 2) + half*8;
            *(float2*)(ctx_out + (size_t)(b*SEQ + q)*HID + col)
                = make_float2(acc[s][half*2], acc[s][half*2+1]);
        }
    }
}

// ---------------------------------------------------------------------------
extern "C" void kernel_launch(void* const* d_in, const int* in_sizes, int n_in,
                              void* d_out, int out_size)
{
    const float* X  = (const float*)d_in[0];
    const float* Wq = (const float*)d_in[1];
    const float* bq = (const float*)d_in[2];
    const float* Wk = (const float*)d_in[3];
    const float* bk = (const float*)d_in[4];
    const float* Wv = (const float*)d_in[5];
    const float* bv = (const float*)d_in[6];

    float* ctx   = (float*)d_out;
    float* probs = (float*)d_out + (size_t)BATCH * SEQ * HID;

    uint32_t* dXs; cudaGetSymbolAddress((void**)&dXs, g_Xs);
    uint32_t* dWs; cudaGetSymbolAddress((void**)&dWs, g_Ws);

    const int nX4 = MTOT * HID / 4, nW4 = HID * HID / 4;
    split_kernel<<<(nX4 + 255)/256, 256>>>(X,  dXs, nX4);
    split_kernel<<<(nW4 + 255)/256, 256>>>(Wq, dWs + 0*(size_t)HID*HID, nW4);
    split_kernel<<<(nW4 + 255)/256, 256>>>(Wk, dWs + 1*(size_t)HID*HID, nW4);
    split_kernel<<<(nW4 + 255)/256, 256>>>(Wv, dWs + 2*(size_t)HID*HID, nW4);

    dim3 qkv_grid(HID/64, MTOT/64, 3);
    qkv_t_kernel<<<qkv_grid, 256>>>(bq, bk, bv);

    dim3 att_grid(SEQ/64, BH);
    scores_t_kernel<<<att_grid, 256>>>(probs);
    pv_t_kernel<<<att_grid, 256>>>(ctx, probs);
}